// round 6
// baseline (speedup 1.0000x reference)
#include <cuda_runtime.h>
#include <cuda_bf16.h>
#include <cuda_fp16.h>

// Problem constants (EdgeConv_33930241638504): N=50000, E=800000, IN=OUT=16, T=8
#define MAXN 50048
#define MAXE 800000
#define IN_F 16
#define OUT_F 16
#define T_F 8
#define LN_EPS 1e-5f

// Scratch (device globals: allocation-free rule)
// g fp16, layout [n][j=t/2][o][s=t&1]: half index = n*128 + j*32 + o*2 + s.
__device__ __half   g_gh[MAXN * T_F * OUT_F];     // 12.8 MB
__device__ float    g_c[MAXN * OUT_F];            // 3.2 MB
__device__ int      g_idx64;                      // 1 if edge_index int64, 0 if int32
__device__ unsigned g_cnt[MAXN];                  // per-src histogram
__device__ unsigned g_cur[MAXN];                  // per-src local-exclusive offsets / cursors
__device__ unsigned g_bsum[256];                  // per-256-bin block sums
__device__ unsigned g_boff[256];                  // block offsets
__device__ uint4    g_rec[(size_t)MAXE * 2];      // 32B records {src,dst,ea fp16 x8} (25.6 MB)

// ---------------------------------------------------------------------------
// Kernel 1: per-node preprocessing (+ dtype detection + histogram zeroing).
// ---------------------------------------------------------------------------
__global__ __launch_bounds__(256) void node_kernel(
    const float* __restrict__ x,
    const float* __restrict__ ln_gamma,
    const float* __restrict__ ln_beta,
    const float* __restrict__ w_edge,
    const float* __restrict__ b_edge,
    const float* __restrict__ root,
    const float* __restrict__ bias,
    const unsigned int* __restrict__ idx_raw,
    float* __restrict__ out,
    int N)
{
    __shared__ float Ws[T_F * IN_F * OUT_F];
    __shared__ float Bs[IN_F * OUT_F];
    __shared__ float Rs[IN_F * OUT_F];
    __shared__ __half Gs[8 * 256];

    for (int i = threadIdx.x; i < T_F * IN_F * OUT_F; i += blockDim.x) Ws[i] = w_edge[i];
    for (int i = threadIdx.x; i < IN_F * OUT_F; i += blockDim.x) { Bs[i] = b_edge[i]; Rs[i] = root[i]; }

    // dtype detection (block 0, warp 0): int64 LE with values < N => odd words zero.
    if (blockIdx.x == 0 && threadIdx.x < 32) {
        int lane = threadIdx.x;
        unsigned int any = 0;
        #pragma unroll
        for (int k = 0; k < 8; k++) any |= idx_raw[2 * (lane * 8 + k) + 1];
        unsigned int ballot = __ballot_sync(0xffffffffu, any != 0);
        if (lane == 0) g_idx64 = (ballot == 0u) ? 1 : 0;
    }

    int gtid = blockIdx.x * blockDim.x + threadIdx.x;
    if (gtid < N) g_cnt[gtid] = 0u;    // zero histogram for the next kernel
    __syncthreads();

    int node = gtid >> 4;
    int o    = gtid & 15;
    bool valid = (node < N);
    int n = valid ? node : (N - 1);

    float xv = x[n * IN_F + o];

    float s = xv;
    #pragma unroll
    for (int off = 8; off > 0; off >>= 1) s += __shfl_xor_sync(0xffffffffu, s, off, 16);
    float mu = s * (1.0f / 16.0f);
    float d = xv - mu;
    float v = d * d;
    #pragma unroll
    for (int off = 8; off > 0; off >>= 1) v += __shfl_xor_sync(0xffffffffu, v, off, 16);
    float var = v * (1.0f / 16.0f);
    float rstd = rsqrtf(var + LN_EPS);

    float h_own = d * rstd * ln_gamma[o] + ln_beta[o];
    h_own = fmaxf(h_own, 0.0f);

    float hv[IN_F];
    #pragma unroll
    for (int i = 0; i < IN_F; i++) hv[i] = __shfl_sync(0xffffffffu, h_own, i, 16);

    int warp = threadIdx.x >> 5;
    int lane = threadIdx.x & 31;
    int local_node = (threadIdx.x >> 4) & 1;
    __half* gw = Gs + warp * 256;
    #pragma unroll
    for (int t = 0; t < T_F; t++) {
        float acc = 0.0f;
        #pragma unroll
        for (int i = 0; i < IN_F; i++) acc = fmaf(hv[i], Ws[t * 256 + i * 16 + o], acc);
        gw[local_node * 128 + (t >> 1) * 32 + o * 2 + (t & 1)] = __float2half(acc);
    }
    __syncwarp();

    int first_node = (blockIdx.x * (blockDim.x >> 4)) + warp * 2;
    int covered = first_node + (lane >> 4);
    if (covered < N) {
        uint4 sv = ((const uint4*)gw)[lane];
        *((uint4*)(g_gh + (long)first_node * 128 + lane * 8)) = sv;
    }

    float cacc = 0.0f;
    #pragma unroll
    for (int i = 0; i < IN_F; i++) cacc = fmaf(hv[i], Bs[i * 16 + o], cacc);
    if (valid) g_c[n * OUT_F + o] = cacc;

    float bacc = bias[o];
    #pragma unroll
    for (int i = 0; i < IN_F; i++) bacc = fmaf(hv[i], Rs[i * 16 + o], bacc);
    if (valid) out[n * OUT_F + o] = bacc;
}

// ---------------------------------------------------------------------------
// Kernel 2: histogram of src.
// ---------------------------------------------------------------------------
__global__ __launch_bounds__(256) void hist_kernel(const void* __restrict__ ei, int E)
{
    int e = blockIdx.x * blockDim.x + threadIdx.x;
    if (e >= E) return;
    int src = g_idx64 ? (int)((const long long*)ei)[e] : ((const int*)ei)[e];
    atomicAdd(&g_cnt[src], 1u);
}

// ---------------------------------------------------------------------------
// Kernels 3+4: two-level exclusive scan of g_cnt.
// scanA: per-256-bin block local exclusive scan -> g_cur, block sums -> g_bsum
// scanB: exclusive scan of block sums -> g_boff
// ---------------------------------------------------------------------------
__global__ void scanA_kernel(int N)
{
    __shared__ unsigned s[256];
    int t = threadIdx.x;
    int idx = blockIdx.x * 256 + t;
    unsigned v = (idx < N) ? g_cnt[idx] : 0u;
    s[t] = v;
    __syncthreads();
    #pragma unroll
    for (int off = 1; off < 256; off <<= 1) {
        unsigned add = (t >= off) ? s[t - off] : 0u;
        __syncthreads();
        s[t] += add;
        __syncthreads();
    }
    unsigned excl = s[t] - v;
    if (idx < N) g_cur[idx] = excl;
    if (t == 255) g_bsum[blockIdx.x] = s[t];
}

__global__ void scanB_kernel(int nb)
{
    __shared__ unsigned s[256];
    int t = threadIdx.x;
    unsigned v = (t < nb) ? g_bsum[t] : 0u;
    s[t] = v;
    __syncthreads();
    #pragma unroll
    for (int off = 1; off < 256; off <<= 1) {
        unsigned add = (t >= off) ? s[t - off] : 0u;
        __syncthreads();
        s[t] += add;
        __syncthreads();
    }
    if (t < nb) g_boff[t] = s[t] - v;
}

// ---------------------------------------------------------------------------
// Kernel 5: scatter edges into src-sorted records.
// Record (32B): {src, dst, ea[0..3] as 2x half2, ea[4..7] as 2x half2, pad}
// ---------------------------------------------------------------------------
__global__ __launch_bounds__(256) void scatter_kernel(
    const void* __restrict__ ei,
    const float* __restrict__ edge_attr,
    int E)
{
    int e = blockIdx.x * blockDim.x + threadIdx.x;
    if (e >= E) return;
    int src, dst;
    if (g_idx64) {
        const long long* p = (const long long*)ei;
        src = (int)p[e];
        dst = (int)p[(long)E + e];
    } else {
        const int* p = (const int*)ei;
        src = p[e];
        dst = p[E + e];
    }
    const float4* eap = (const float4*)(edge_attr + (long)e * T_F);
    float4 e0 = eap[0];
    float4 e1 = eap[1];
    __half2 h01 = __floats2half2_rn(e0.x, e0.y);
    __half2 h23 = __floats2half2_rn(e0.z, e0.w);
    __half2 h45 = __floats2half2_rn(e1.x, e1.y);
    __half2 h67 = __floats2half2_rn(e1.z, e1.w);

    unsigned local = atomicAdd(&g_cur[src], 1u);
    size_t p = (size_t)g_boff[src >> 8] + local;

    uint4 lo;
    lo.x = (unsigned)src;
    lo.y = (unsigned)dst;
    lo.z = *(unsigned*)&h01;
    lo.w = *(unsigned*)&h23;
    g_rec[2 * p] = lo;
    uint2 hi;
    hi.x = *(unsigned*)&h45;
    hi.y = *(unsigned*)&h67;
    *((uint2*)&g_rec[2 * p + 1]) = hi;
}

// ---------------------------------------------------------------------------
// Kernel 6: per-edge message + scatter, src-sorted order.
// 4 lanes per edge; lane q owns outputs [4q, 4q+4). Consecutive quads share
// src -> g/c gathers hit L1 / broadcast.
// ---------------------------------------------------------------------------
__global__ __launch_bounds__(256) void edge2_kernel(float* __restrict__ out, int E)
{
    int tid = blockIdx.x * blockDim.x + threadIdx.x;
    int p = tid >> 2;
    int q = tid & 3;
    if (p >= E) return;

    uint4 lo = g_rec[2 * (size_t)p];
    uint2 hi = *((const uint2*)&g_rec[2 * (size_t)p + 1]);
    int src = (int)lo.x;
    int dst = (int)lo.y;

    float2 a01 = __half22float2(*(__half2*)&lo.z);
    float2 a23 = __half22float2(*(__half2*)&lo.w);
    float2 a45 = __half22float2(*(__half2*)&hi.x);
    float2 a67 = __half22float2(*(__half2*)&hi.y);
    float eat[T_F] = {a01.x, a01.y, a23.x, a23.y, a45.x, a45.y, a67.x, a67.y};

    const float4* c4 = (const float4*)g_c;
    float4 m = c4[src * 4 + q];

    const uint4* g4 = (const uint4*)(g_gh + (size_t)src * 128);
    #pragma unroll
    for (int j = 0; j < 4; j++) {
        uint4 u = g4[j * 4 + q];
        float a0 = eat[2 * j];
        float a1 = eat[2 * j + 1];
        float2 pp;
        pp = __half22float2(*(const __half2*)&u.x);
        m.x = fmaf(a0, pp.x, fmaf(a1, pp.y, m.x));
        pp = __half22float2(*(const __half2*)&u.y);
        m.y = fmaf(a0, pp.x, fmaf(a1, pp.y, m.y));
        pp = __half22float2(*(const __half2*)&u.z);
        m.z = fmaf(a0, pp.x, fmaf(a1, pp.y, m.z));
        pp = __half22float2(*(const __half2*)&u.w);
        m.w = fmaf(a0, pp.x, fmaf(a1, pp.y, m.w));
    }

    float* dstp = out + (size_t)dst * OUT_F + q * 4;
    asm volatile("red.global.add.v4.f32 [%0], {%1, %2, %3, %4};"
                 :: "l"(dstp), "f"(m.x), "f"(m.y), "f"(m.z), "f"(m.w)
                 : "memory");
}

// ---------------------------------------------------------------------------
extern "C" void kernel_launch(void* const* d_in, const int* in_sizes, int n_in,
                              void* d_out, int out_size)
{
    const float* x        = (const float*)d_in[0];
    const void*  eidx     = d_in[1];
    const float* eattr    = (const float*)d_in[2];
    const float* ln_gamma = (const float*)d_in[3];
    const float* ln_beta  = (const float*)d_in[4];
    const float* w_edge   = (const float*)d_in[5];
    const float* b_edge   = (const float*)d_in[6];
    const float* root     = (const float*)d_in[7];
    const float* bias     = (const float*)d_in[8];
    float* out = (float*)d_out;

    int N = in_sizes[0] / IN_F;
    int E = in_sizes[1] / 2;
    int nb = (N + 255) >> 8;   // number of 256-bins (<= 256 for N <= 65536)

    {
        int threads = N * 16;
        int grid = (threads + 255) / 256;
        node_kernel<<<grid, 256>>>(x, ln_gamma, ln_beta, w_edge, b_edge, root, bias,
                                   (const unsigned int*)eidx, out, N);
    }
    hist_kernel<<<(E + 255) / 256, 256>>>(eidx, E);
    scanA_kernel<<<nb, 256>>>(N);
    scanB_kernel<<<1, 256>>>(nb);
    scatter_kernel<<<(E + 255) / 256, 256>>>(eidx, eattr, E);
    edge2_kernel<<<(E * 4 + 255) / 256, 256>>>(out, E);
}

// round 7
// speedup vs baseline: 1.9294x; 1.9294x over previous
#include <cuda_runtime.h>
#include <cuda_bf16.h>
#include <cuda_fp16.h>

// Problem constants (EdgeConv_33930241638504): N=50000, E=800000, IN=OUT=16, T=8
#define MAXN 50048
#define IN_F 16
#define OUT_F 16
#define T_F 8
#define LN_EPS 1e-5f

// Scratch (device globals: allocation-free rule)
// Per-node 288B record, fp16:
//   halves [0..127]  : g[n][j=t/2][o][s=t&1]  (half idx = j*32 + o*2 + s)
//   halves [128..143]: c[n][o]
// Quad lane q reads g chunk (j): 16B at j*32+q*8 -> 64B contiguous per j,
// and c: 8B at 256B + q*8 -> 32B contiguous.
__device__ __half g_ghc[(size_t)MAXN * 144];   // 14.4 MB (L2-resident)
__device__ int    g_idx64;                     // 1 if edge_index int64, 0 if int32

// ---------------------------------------------------------------------------
// Kernel 1: per-node preprocessing (+ inline edge_index dtype detection).
// 16 lanes per node; lane = o. h = relu(LN(x));
//   g[n,t,o] = sum_i h[i]*W[t,i,o]   (fp16, staged via smem)
//   c[n,o]   = sum_i h[i]*b_edge[i,o] (fp16, appended to g block)
//   out[n,o] = sum_i h[i]*root[i,o] + bias[o]
// W/B/R transposed in smem to [t][o][i] (pad 20) -> 4x LDS.128 per dot product.
// ---------------------------------------------------------------------------
#define OPAD 20
__global__ __launch_bounds__(256) void node_kernel(
    const float* __restrict__ x,
    const float* __restrict__ ln_gamma,
    const float* __restrict__ ln_beta,
    const float* __restrict__ w_edge,   // [T, IN*OUT] = 2048 floats
    const float* __restrict__ b_edge,   // [IN*OUT]
    const float* __restrict__ root,     // [IN, OUT]
    const float* __restrict__ bias,     // [OUT]
    const unsigned int* __restrict__ idx_raw,
    float* __restrict__ out,
    int N)
{
    __shared__ float Wt[T_F * IN_F * OPAD];   // [t][o*20 + i]   2560 floats
    __shared__ float Bt[IN_F * OPAD];         // [o*20 + i]       320
    __shared__ float Rt[IN_F * OPAD];         // [o*20 + i]       320
    __shared__ __half Gs[8 * 288];            // 8 warps x (2 nodes x 144 halves)

    for (int idx = threadIdx.x; idx < T_F * IN_F * OUT_F; idx += blockDim.x) {
        int t = idx >> 8, rem = idx & 255, i = rem >> 4, o = rem & 15;
        Wt[t * (IN_F * OPAD) + o * OPAD + i] = w_edge[idx];
    }
    for (int idx = threadIdx.x; idx < IN_F * OUT_F; idx += blockDim.x) {
        int i = idx >> 4, o = idx & 15;
        Bt[o * OPAD + i] = b_edge[idx];
        Rt[o * OPAD + i] = root[idx];
    }

    // dtype detection (block 0, warp 0): int64 LE with values < N => odd words zero.
    if (blockIdx.x == 0 && threadIdx.x < 32) {
        int lane = threadIdx.x;
        unsigned int any = 0;
        #pragma unroll
        for (int k = 0; k < 8; k++) any |= idx_raw[2 * (lane * 8 + k) + 1];
        unsigned int ballot = __ballot_sync(0xffffffffu, any != 0);
        if (lane == 0) g_idx64 = (ballot == 0u) ? 1 : 0;
    }
    __syncthreads();

    int gtid = blockIdx.x * blockDim.x + threadIdx.x;
    int node = gtid >> 4;
    int o    = gtid & 15;
    bool valid = (node < N);
    int n = valid ? node : (N - 1);

    float xv = x[n * IN_F + o];

    // LayerNorm over the 16-lane segment
    float s = xv;
    #pragma unroll
    for (int off = 8; off > 0; off >>= 1) s += __shfl_xor_sync(0xffffffffu, s, off, 16);
    float mu = s * (1.0f / 16.0f);
    float d = xv - mu;
    float v = d * d;
    #pragma unroll
    for (int off = 8; off > 0; off >>= 1) v += __shfl_xor_sync(0xffffffffu, v, off, 16);
    float var = v * (1.0f / 16.0f);
    float rstd = rsqrtf(var + LN_EPS);

    float h_own = d * rstd * ln_gamma[o] + ln_beta[o];
    h_own = fmaxf(h_own, 0.0f);

    // node's h vector as 4 float4s (shuffle-gathered)
    float4 h4[4];
    {
        float hv[IN_F];
        #pragma unroll
        for (int i = 0; i < IN_F; i++) hv[i] = __shfl_sync(0xffffffffu, h_own, i, 16);
        #pragma unroll
        for (int k = 0; k < 4; k++) h4[k] = make_float4(hv[4*k], hv[4*k+1], hv[4*k+2], hv[4*k+3]);
    }

    int warp = threadIdx.x >> 5;
    int lane = threadIdx.x & 31;
    int local_node = (threadIdx.x >> 4) & 1;
    __half* gw = Gs + warp * 288;

    // g: for each t, dot(h, W[t][:,o]) via 4x LDS.128
    #pragma unroll
    for (int t = 0; t < T_F; t++) {
        const float4* wrow = (const float4*)&Wt[t * (IN_F * OPAD) + o * OPAD];
        float acc = 0.0f;
        #pragma unroll
        for (int k = 0; k < 4; k++) {
            float4 w = wrow[k];
            acc = fmaf(h4[k].x, w.x, acc);
            acc = fmaf(h4[k].y, w.y, acc);
            acc = fmaf(h4[k].z, w.z, acc);
            acc = fmaf(h4[k].w, w.w, acc);
        }
        gw[local_node * 144 + (t >> 1) * 32 + o * 2 + (t & 1)] = __float2half(acc);
    }

    // c (fp16, appended)
    {
        const float4* brow = (const float4*)&Bt[o * OPAD];
        float acc = 0.0f;
        #pragma unroll
        for (int k = 0; k < 4; k++) {
            float4 w = brow[k];
            acc = fmaf(h4[k].x, w.x, acc);
            acc = fmaf(h4[k].y, w.y, acc);
            acc = fmaf(h4[k].z, w.z, acc);
            acc = fmaf(h4[k].w, w.w, acc);
        }
        gw[local_node * 144 + 128 + o] = __float2half(acc);
    }
    __syncwarp();

    // write-out: warp's 2 nodes = 576B = 36 uint4. Lane k covers node k>=18.
    int first_node = blockIdx.x * 16 + warp * 2;
    #pragma unroll
    for (int k = lane; k < 36; k += 32) {
        int covered = first_node + (k >= 18 ? 1 : 0);
        if (covered < N) {
            uint4 sv = ((const uint4*)gw)[k];
            ((uint4*)(g_ghc + (size_t)first_node * 144))[k] = sv;
        }
    }

    // out init: root transform + bias (fp32)
    {
        const float4* rrow = (const float4*)&Rt[o * OPAD];
        float acc = bias[o];
        #pragma unroll
        for (int k = 0; k < 4; k++) {
            float4 w = rrow[k];
            acc = fmaf(h4[k].x, w.x, acc);
            acc = fmaf(h4[k].y, w.y, acc);
            acc = fmaf(h4[k].z, w.z, acc);
            acc = fmaf(h4[k].w, w.w, acc);
        }
        if (valid) out[n * OUT_F + o] = acc;
    }
}

// ---------------------------------------------------------------------------
// Kernel 2: per-edge message + scatter.
// 4 lanes per edge; lane q owns outputs [4q, 4q+4).
//   msg[o] = c[src,o] + sum_t ea[t]*g[src,t,o]
// Gathers one contiguous 288B record per src.
// ---------------------------------------------------------------------------
__global__ __launch_bounds__(256) void edge_kernel(
    const void* __restrict__ edge_index,       // [2, E] int64 OR int32
    const float* __restrict__ edge_attr,       // [E, 8]
    float* __restrict__ out,
    int E)
{
    int tid = blockIdx.x * blockDim.x + threadIdx.x;
    int e = tid >> 2;
    int q = tid & 3;
    if (e >= E) return;

    int src, dst;
    if (g_idx64) {
        const long long* ei = (const long long*)edge_index;
        src = (int)ei[e];
        dst = (int)ei[(long)E + e];
    } else {
        const int* ei = (const int*)edge_index;
        src = ei[e];
        dst = ei[E + e];
    }

    // edge attributes (same addr within quad -> broadcast)
    const float4* eap = (const float4*)(edge_attr + (long)e * T_F);
    float4 ea0 = eap[0];
    float4 ea1 = eap[1];
    float eat[T_F] = {ea0.x, ea0.y, ea0.z, ea0.w, ea1.x, ea1.y, ea1.z, ea1.w};

    const __half* rec = g_ghc + (size_t)src * 144;

    // c: 8B at byte offset 256 + q*8
    float4 m;
    {
        uint2 cu = ((const uint2*)rec)[32 + q];
        float2 c01 = __half22float2(*(const __half2*)&cu.x);
        float2 c23 = __half22float2(*(const __half2*)&cu.y);
        m = make_float4(c01.x, c01.y, c23.x, c23.y);
    }

    // g: chunk j at uint4 index j*4 + q; u.{x,y,z,w} = half2 {t=2j, t=2j+1}
    const uint4* g4 = (const uint4*)rec;
    #pragma unroll
    for (int j = 0; j < 4; j++) {
        uint4 u = g4[j * 4 + q];
        float a0 = eat[2 * j];
        float a1 = eat[2 * j + 1];
        float2 p;
        p = __half22float2(*(const __half2*)&u.x);
        m.x = fmaf(a0, p.x, fmaf(a1, p.y, m.x));
        p = __half22float2(*(const __half2*)&u.y);
        m.y = fmaf(a0, p.x, fmaf(a1, p.y, m.y));
        p = __half22float2(*(const __half2*)&u.z);
        m.z = fmaf(a0, p.x, fmaf(a1, p.y, m.z));
        p = __half22float2(*(const __half2*)&u.w);
        m.w = fmaf(a0, p.x, fmaf(a1, p.y, m.w));
    }

    float* dstp = out + (size_t)dst * OUT_F + q * 4;
    asm volatile("red.global.add.v4.f32 [%0], {%1, %2, %3, %4};"
                 :: "l"(dstp), "f"(m.x), "f"(m.y), "f"(m.z), "f"(m.w)
                 : "memory");
}

// ---------------------------------------------------------------------------
extern "C" void kernel_launch(void* const* d_in, const int* in_sizes, int n_in,
                              void* d_out, int out_size)
{
    const float* x        = (const float*)d_in[0];
    const void*  eidx     = d_in[1];
    const float* eattr    = (const float*)d_in[2];
    const float* ln_gamma = (const float*)d_in[3];
    const float* ln_beta  = (const float*)d_in[4];
    const float* w_edge   = (const float*)d_in[5];
    const float* b_edge   = (const float*)d_in[6];
    const float* root     = (const float*)d_in[7];
    const float* bias     = (const float*)d_in[8];
    float* out = (float*)d_out;

    int N = in_sizes[0] / IN_F;
    int E = in_sizes[1] / 2;

    {
        int threads = N * 16;
        int grid = (threads + 255) / 256;
        node_kernel<<<grid, 256>>>(x, ln_gamma, ln_beta, w_edge, b_edge, root, bias,
                                   (const unsigned int*)eidx, out, N);
    }
    edge_kernel<<<(E * 4 + 255) / 256, 256>>>(eidx, eattr, out, E);
}

// round 8
// speedup vs baseline: 1.9864x; 1.0296x over previous
#include <cuda_runtime.h>
#include <cuda_bf16.h>
#include <cuda_fp16.h>

// Problem constants (EdgeConv_33930241638504): N=50000, E=800000, IN=OUT=16, T=8
#define MAXN 50048
#define IN_F 16
#define OUT_F 16
#define T_F 8
#define LN_EPS 1e-5f

// Scratch (device globals: allocation-free rule)
// g fp16, 256B/node, layout [n][j=t/2][o][s=t&1]: half idx = n*128 + j*32 + o*2 + s.
// Quad lane q reads chunk (j): 16B at j*32+q*8 -> quad covers contiguous 64B per j.
__device__ __half g_gh[(size_t)MAXN * 128];   // 12.8 MB (L2-resident)
__device__ float  g_c[MAXN * OUT_F];          // c[n][o] fp32 (3.2 MB, L2-resident)
__device__ int    g_idx64;                    // 1 if edge_index int64, 0 if int32

// ---------------------------------------------------------------------------
// Kernel 1: per-node preprocessing (+ inline edge_index dtype detection).
// 16 lanes per node; lane = o. h = relu(LN(x));
//   g[n,t,o] = sum_i h[i]*W[t,i,o]    (fp16, staged via smem -> 1 STG.128/lane)
//   c[n,o]   = sum_i h[i]*b_edge[i,o] (fp32)
//   out[n,o] = sum_i h[i]*root[i,o] + bias[o]
// W/B/R transposed in smem to [t][o][i] (pad 20) -> 4x LDS.128 per dot product.
// ---------------------------------------------------------------------------
#define OPAD 20
__global__ __launch_bounds__(256) void node_kernel(
    const float* __restrict__ x,
    const float* __restrict__ ln_gamma,
    const float* __restrict__ ln_beta,
    const float* __restrict__ w_edge,   // [T, IN*OUT] = 2048 floats
    const float* __restrict__ b_edge,   // [IN*OUT]
    const float* __restrict__ root,     // [IN, OUT]
    const float* __restrict__ bias,     // [OUT]
    const unsigned int* __restrict__ idx_raw,
    float* __restrict__ out,
    int N)
{
    __shared__ float Wt[T_F * IN_F * OPAD];   // [t][o*20 + i]
    __shared__ float Bt[IN_F * OPAD];
    __shared__ float Rt[IN_F * OPAD];
    __shared__ __half Gs[8 * 256];            // 8 warps x (2 nodes x 128 halves)

    for (int idx = threadIdx.x; idx < T_F * IN_F * OUT_F; idx += blockDim.x) {
        int t = idx >> 8, rem = idx & 255, i = rem >> 4, o = rem & 15;
        Wt[t * (IN_F * OPAD) + o * OPAD + i] = w_edge[idx];
    }
    for (int idx = threadIdx.x; idx < IN_F * OUT_F; idx += blockDim.x) {
        int i = idx >> 4, o = idx & 15;
        Bt[o * OPAD + i] = b_edge[idx];
        Rt[o * OPAD + i] = root[idx];
    }

    // dtype detection (block 0, warp 0): int64 LE with values < N => odd words zero.
    if (blockIdx.x == 0 && threadIdx.x < 32) {
        int lane = threadIdx.x;
        unsigned int any = 0;
        #pragma unroll
        for (int k = 0; k < 8; k++) any |= idx_raw[2 * (lane * 8 + k) + 1];
        unsigned int ballot = __ballot_sync(0xffffffffu, any != 0);
        if (lane == 0) g_idx64 = (ballot == 0u) ? 1 : 0;
    }
    __syncthreads();

    int gtid = blockIdx.x * blockDim.x + threadIdx.x;
    int node = gtid >> 4;
    int o    = gtid & 15;
    bool valid = (node < N);
    int n = valid ? node : (N - 1);

    float xv = x[n * IN_F + o];

    // LayerNorm over the 16-lane segment
    float s = xv;
    #pragma unroll
    for (int off = 8; off > 0; off >>= 1) s += __shfl_xor_sync(0xffffffffu, s, off, 16);
    float mu = s * (1.0f / 16.0f);
    float d = xv - mu;
    float v = d * d;
    #pragma unroll
    for (int off = 8; off > 0; off >>= 1) v += __shfl_xor_sync(0xffffffffu, v, off, 16);
    float var = v * (1.0f / 16.0f);
    float rstd = rsqrtf(var + LN_EPS);

    float h_own = d * rstd * ln_gamma[o] + ln_beta[o];
    h_own = fmaxf(h_own, 0.0f);

    // node's h vector as 4 float4s (shuffle-gathered)
    float4 h4[4];
    {
        float hv[IN_F];
        #pragma unroll
        for (int i = 0; i < IN_F; i++) hv[i] = __shfl_sync(0xffffffffu, h_own, i, 16);
        #pragma unroll
        for (int k = 0; k < 4; k++) h4[k] = make_float4(hv[4*k], hv[4*k+1], hv[4*k+2], hv[4*k+3]);
    }

    int warp = threadIdx.x >> 5;
    int lane = threadIdx.x & 31;
    int local_node = (threadIdx.x >> 4) & 1;
    __half* gw = Gs + warp * 256;

    // g: for each t, dot(h, W[t][:,o]) via 4x LDS.128
    #pragma unroll
    for (int t = 0; t < T_F; t++) {
        const float4* wrow = (const float4*)&Wt[t * (IN_F * OPAD) + o * OPAD];
        float acc = 0.0f;
        #pragma unroll
        for (int k = 0; k < 4; k++) {
            float4 w = wrow[k];
            acc = fmaf(h4[k].x, w.x, acc);
            acc = fmaf(h4[k].y, w.y, acc);
            acc = fmaf(h4[k].z, w.z, acc);
            acc = fmaf(h4[k].w, w.w, acc);
        }
        gw[local_node * 128 + (t >> 1) * 32 + o * 2 + (t & 1)] = __float2half(acc);
    }
    __syncwarp();

    // write-out: warp's 2 nodes = 512B = 32 uint4; lane k covers node (k>=16).
    int first_node = blockIdx.x * 16 + warp * 2;
    int covered = first_node + (lane >> 4);
    if (covered < N) {
        uint4 sv = ((const uint4*)gw)[lane];
        ((uint4*)(g_gh + (size_t)first_node * 128))[lane] = sv;
    }

    // c (fp32)
    {
        const float4* brow = (const float4*)&Bt[o * OPAD];
        float acc = 0.0f;
        #pragma unroll
        for (int k = 0; k < 4; k++) {
            float4 w = brow[k];
            acc = fmaf(h4[k].x, w.x, acc);
            acc = fmaf(h4[k].y, w.y, acc);
            acc = fmaf(h4[k].z, w.z, acc);
            acc = fmaf(h4[k].w, w.w, acc);
        }
        if (valid) g_c[n * OUT_F + o] = acc;
    }

    // out init: root transform + bias
    {
        const float4* rrow = (const float4*)&Rt[o * OPAD];
        float acc = bias[o];
        #pragma unroll
        for (int k = 0; k < 4; k++) {
            float4 w = rrow[k];
            acc = fmaf(h4[k].x, w.x, acc);
            acc = fmaf(h4[k].y, w.y, acc);
            acc = fmaf(h4[k].z, w.z, acc);
            acc = fmaf(h4[k].w, w.w, acc);
        }
        if (valid) out[n * OUT_F + o] = acc;
    }
}

// ---------------------------------------------------------------------------
// Kernel 2: per-edge message + scatter, 2 edges per thread for MLP.
// Quad q handles edges e0 = p and e1 = p + halfE (two independent streams).
//   msg[o] = c[src,o] + sum_t ea[t]*g[src,t,o]
// ---------------------------------------------------------------------------
__global__ __launch_bounds__(256) void edge_kernel(
    const void* __restrict__ edge_index,       // [2, E] int64 OR int32
    const float* __restrict__ edge_attr,       // [E, 8]
    float* __restrict__ out,
    int E, int halfE)
{
    int tid = blockIdx.x * blockDim.x + threadIdx.x;
    int p = tid >> 2;
    int q = tid & 3;
    if (p >= halfE) return;

    int e0 = p;
    int e1 = p + halfE;
    bool has1 = (e1 < E);
    int e1c = has1 ? e1 : e0;

    int src0, dst0, src1, dst1;
    if (g_idx64) {
        const long long* ei = (const long long*)edge_index;
        src0 = (int)ei[e0];             dst0 = (int)ei[(long)E + e0];
        src1 = (int)ei[e1c];            dst1 = (int)ei[(long)E + e1c];
    } else {
        const int* ei = (const int*)edge_index;
        src0 = ei[e0];                  dst0 = ei[E + e0];
        src1 = ei[e1c];                 dst1 = ei[E + e1c];
    }

    // edge attributes (same addr within quad -> broadcast)
    const float4* eap = (const float4*)edge_attr;
    float4 a00 = eap[(long)e0 * 2];
    float4 a01 = eap[(long)e0 * 2 + 1];
    float4 a10 = eap[(long)e1c * 2];
    float4 a11 = eap[(long)e1c * 2 + 1];
    float ea0[T_F] = {a00.x, a00.y, a00.z, a00.w, a01.x, a01.y, a01.z, a01.w};
    float ea1[T_F] = {a10.x, a10.y, a10.z, a10.w, a11.x, a11.y, a11.z, a11.w};

    // c (fp32, L2-resident)
    const float4* c4 = (const float4*)g_c;
    float4 m0 = c4[src0 * 4 + q];
    float4 m1 = c4[src1 * 4 + q];

    // g gathers: 8 independent LDG.128 (4 per edge)
    const uint4* g40 = (const uint4*)(g_gh + (size_t)src0 * 128);
    const uint4* g41 = (const uint4*)(g_gh + (size_t)src1 * 128);
    uint4 u0[4], u1[4];
    #pragma unroll
    for (int j = 0; j < 4; j++) { u0[j] = g40[j * 4 + q]; u1[j] = g41[j * 4 + q]; }

    #pragma unroll
    for (int j = 0; j < 4; j++) {
        float b0 = ea0[2 * j], b1 = ea0[2 * j + 1];
        float2 pp;
        pp = __half22float2(*(const __half2*)&u0[j].x);
        m0.x = fmaf(b0, pp.x, fmaf(b1, pp.y, m0.x));
        pp = __half22float2(*(const __half2*)&u0[j].y);
        m0.y = fmaf(b0, pp.x, fmaf(b1, pp.y, m0.y));
        pp = __half22float2(*(const __half2*)&u0[j].z);
        m0.z = fmaf(b0, pp.x, fmaf(b1, pp.y, m0.z));
        pp = __half22float2(*(const __half2*)&u0[j].w);
        m0.w = fmaf(b0, pp.x, fmaf(b1, pp.y, m0.w));

        float d0 = ea1[2 * j], d1 = ea1[2 * j + 1];
        pp = __half22float2(*(const __half2*)&u1[j].x);
        m1.x = fmaf(d0, pp.x, fmaf(d1, pp.y, m1.x));
        pp = __half22float2(*(const __half2*)&u1[j].y);
        m1.y = fmaf(d0, pp.x, fmaf(d1, pp.y, m1.y));
        pp = __half22float2(*(const __half2*)&u1[j].z);
        m1.z = fmaf(d0, pp.x, fmaf(d1, pp.y, m1.z));
        pp = __half22float2(*(const __half2*)&u1[j].w);
        m1.w = fmaf(d0, pp.x, fmaf(d1, pp.y, m1.w));
    }

    float* dp0 = out + (size_t)dst0 * OUT_F + q * 4;
    asm volatile("red.global.add.v4.f32 [%0], {%1, %2, %3, %4};"
                 :: "l"(dp0), "f"(m0.x), "f"(m0.y), "f"(m0.z), "f"(m0.w)
                 : "memory");
    if (has1) {
        float* dp1 = out + (size_t)dst1 * OUT_F + q * 4;
        asm volatile("red.global.add.v4.f32 [%0], {%1, %2, %3, %4};"
                     :: "l"(dp1), "f"(m1.x), "f"(m1.y), "f"(m1.z), "f"(m1.w)
                     : "memory");
    }
}

// ---------------------------------------------------------------------------
extern "C" void kernel_launch(void* const* d_in, const int* in_sizes, int n_in,
                              void* d_out, int out_size)
{
    const float* x        = (const float*)d_in[0];
    const void*  eidx     = d_in[1];
    const float* eattr    = (const float*)d_in[2];
    const float* ln_gamma = (const float*)d_in[3];
    const float* ln_beta  = (const float*)d_in[4];
    const float* w_edge   = (const float*)d_in[5];
    const float* b_edge   = (const float*)d_in[6];
    const float* root     = (const float*)d_in[7];
    const float* bias     = (const float*)d_in[8];
    float* out = (float*)d_out;

    int N = in_sizes[0] / IN_F;
    int E = in_sizes[1] / 2;
    int halfE = (E + 1) / 2;

    {
        int threads = N * 16;
        int grid = (threads + 255) / 256;
        node_kernel<<<grid, 256>>>(x, ln_gamma, ln_beta, w_edge, b_edge, root, bias,
                                   (const unsigned int*)eidx, out, N);
    }
    edge_kernel<<<(halfE * 4 + 255) / 256, 256>>>(eidx, eattr, out, E, halfE);
}